// round 7
// baseline (speedup 1.0000x reference)
#include <cuda_runtime.h>
#include <cstdint>

#define S_  512
#define B_  64
#define C_  1024
#define V_  10
#define TS_ 128
#define K_  64            // chunk length
#define NQ_ (S_ / K_)     // 8 chunks
#define LN_EPS_ 1e-5f

typedef unsigned long long ull;

// Scratch (allocation-free rule: __device__ globals)
// g_Pt: per (b,q) pos tile, 64 rows x 140 words, slot s stored at word s + 4*(s>>5)
__device__ float  g_Pt[(size_t)B_ * NQ_ * 64 * 140];   // ~18.3 MB
__device__ float4 g_hd[(size_t)S_ * B_];               // (d0,d1,d2,w)
__device__ float  g_Gd[(size_t)B_ * NQ_ * 512];        // diag 8x8 Gram blocks (1 MB)
__device__ float  g_tape[(size_t)TS_ * B_ * C_];       // final tape [l][b][c] (32 MB)

// ---- packed fp32x2 helpers ----
__device__ __forceinline__ ull fma2(ull a, ull b, ull c) {
    ull d;
    asm("fma.rn.f32x2 %0, %1, %2, %3;" : "=l"(d) : "l"(a), "l"(b), "l"(c));
    return d;
}
__device__ __forceinline__ ull add2(ull a, ull b) {
    ull d;
    asm("add.rn.f32x2 %0, %1, %2;" : "=l"(d) : "l"(a), "l"(b));
    return d;
}
__device__ __forceinline__ ull pk2(float lo, float hi) {
    ull r;
    asm("mov.b64 %0, {%1, %2};" : "=l"(r) : "f"(lo), "f"(hi));
    return r;
}
__device__ __forceinline__ float2 upk2(ull x) {
    float2 r;
    asm("mov.b64 {%0, %1}, %2;" : "=f"(r.x), "=f"(r.y) : "l"(x));
    return r;
}
__device__ __forceinline__ void cpa16(uint32_t s, const void* g) {
    asm volatile("cp.async.ca.shared.global [%0], [%1], 16;" :: "r"(s), "l"(g));
}
__device__ __forceinline__ void cpa_wait() {
    asm volatile("cp.async.commit_group;");
    asm volatile("cp.async.wait_group 0;" ::: "memory");
}
__device__ __forceinline__ uint32_t smem_u32(const void* p) {
    uint32_t a;
    asm("{ .reg .u64 t; cvta.to.shared.u64 t, %1; cvt.u32.u64 %0, t; }" : "=r"(a) : "l"(p));
    return a;
}

// ---------------------------------------------------------------------------
// Phase A: heads. dir = softmax(v@Wd^T+bd), w = sigmoid(v@Wr[1]+br[1]).
// ---------------------------------------------------------------------------
__global__ void __launch_bounds__(256) heads_kernel(
    const float* __restrict__ vals,
    const float* __restrict__ Wd, const float* __restrict__ bd,
    const float* __restrict__ Wr, const float* __restrict__ br)
{
    __shared__ float sW[4 * C_];
    int tid = threadIdx.x;
    for (int i = tid; i < 3 * C_; i += 256) sW[i] = Wd[i];
    for (int i = tid; i < C_;     i += 256) sW[3 * C_ + i] = Wr[C_ + i];
    __syncthreads();

    int warp = tid >> 5, lane = tid & 31;
    int row = blockIdx.x * 8 + warp;               // row = t*B + b
    const float4* v4 = reinterpret_cast<const float4*>(vals + (size_t)row * C_);
    const float4* w4 = reinterpret_cast<const float4*>(sW);

    float a0 = 0.f, a1 = 0.f, a2 = 0.f, a3 = 0.f;
    for (int i = lane; i < C_ / 4; i += 32) {
        float4 v = v4[i];
        float4 w;
        w = w4[i];       a0 += v.x*w.x + v.y*w.y + v.z*w.z + v.w*w.w;
        w = w4[256 + i]; a1 += v.x*w.x + v.y*w.y + v.z*w.z + v.w*w.w;
        w = w4[512 + i]; a2 += v.x*w.x + v.y*w.y + v.z*w.z + v.w*w.w;
        w = w4[768 + i]; a3 += v.x*w.x + v.y*w.y + v.z*w.z + v.w*w.w;
    }
    #pragma unroll
    for (int o = 16; o; o >>= 1) {
        a0 += __shfl_xor_sync(0xffffffffu, a0, o);
        a1 += __shfl_xor_sync(0xffffffffu, a1, o);
        a2 += __shfl_xor_sync(0xffffffffu, a2, o);
        a3 += __shfl_xor_sync(0xffffffffu, a3, o);
    }
    if (lane == 0) {
        float z0 = a0 + bd[0], z1 = a1 + bd[1], z2 = a2 + bd[2];
        float m  = fmaxf(z0, fmaxf(z1, z2));
        float e0 = expf(z0 - m), e1 = expf(z1 - m), e2 = expf(z2 - m);
        float inv = 1.f / (e0 + e1 + e2);
        float wg  = 1.f / (1.f + expf(-(a3 + br[1])));
        g_hd[row] = make_float4(e0 * inv, e1 * inv, e2 * inv, wg);
    }
}

// ---------------------------------------------------------------------------
// Phase B: pos evolution. One warp per batch, 4 slots/lane, shuffle neighbors.
// Writes the per-(b,chunk) swizzled tile: row stride 140, slot s at word
// s + 4*(s>>5)  (lane's 4 slots s=lane*4.. stay in one 32-slot quarter).
// ---------------------------------------------------------------------------
__global__ void __launch_bounds__(256) pos_kernel()
{
    int warp = threadIdx.x >> 5, lane = threadIdx.x & 31;
    int b = blockIdx.x * 8 + warp;
    float p0 = (lane == 0) ? 1.f : 0.f, p1 = 0.f, p2 = 0.f, p3 = 0.f;
    int woff = lane * 4 + 4 * (lane >> 3);

    float4 D0 = g_hd[0 * B_ + b];
    float4 D1 = g_hd[1 * B_ + b];
    float4 D2 = g_hd[2 * B_ + b];
    float4 D3 = g_hd[3 * B_ + b];

    for (int t = 0; t < S_; t += 4) {
        #pragma unroll
        for (int k = 0; k < 4; k++) {
            int tt = t + k;
            float* dst = g_Pt + ((size_t)(b * NQ_ + (tt >> 6)) * 64 + (tt & 63)) * 140 + woff;
            *reinterpret_cast<float4*>(dst) = make_float4(p0, p1, p2, p3);
            float4 Dk = (k == 0) ? D0 : (k == 1) ? D1 : (k == 2) ? D2 : D3;
            float4 Dn = g_hd[(size_t)min(tt + 4, S_ - 1) * B_ + b];
            if (k == 0) D0 = Dn; else if (k == 1) D1 = Dn; else if (k == 2) D2 = Dn; else D3 = Dn;
            float d0 = Dk.x, d1 = Dk.y, d2 = Dk.z;
            float lw = __shfl_sync(0xffffffffu, p3, (lane + 31) & 31);
            float rw = __shfl_sync(0xffffffffu, p0, (lane + 1)  & 31);
            float n0 = p1 * d0 + p0 * d1 + lw * d2;
            float n1 = p2 * d0 + p1 * d1 + p0 * d2;
            float n2 = p3 * d0 + p2 * d1 + p1 * d2;
            float n3 = rw * d0 + p3 * d1 + p2 * d2;
            p0 = n0; p1 = n1; p2 = n2; p3 = n3;
        }
    }
}

// ---------------------------------------------------------------------------
// Phase B2: diagonal 8x8 Gram blocks from the tiled pos layout.
// ---------------------------------------------------------------------------
__global__ void __launch_bounds__(256) gramd_kernel()
{
    __shared__ float sPg[K_][132];
    int tid = threadIdx.x;
    int T0tile = blockIdx.x;   // = b*NQ + q
    const float* gp = g_Pt + (size_t)T0tile * (64 * 140);

    for (int idx = tid; idx < K_ * TS_; idx += 256) {
        int t = idx >> 7, l = idx & 127;
        sPg[t][l] = gp[t * 140 + l + 4 * (l >> 5)];
    }
    __syncthreads();

    int w = tid >> 5, lane = tid & 31;   // warp w handles group w
    float* out = g_Gd + (size_t)T0tile * 512 + w * 64;
    #pragma unroll
    for (int e = lane; e < 64; e += 32) {
        int jj = e >> 3, j = e & 7;
        const float* ra = sPg[w * 8 + jj];
        const float* rb = sPg[w * 8 + j];
        float d0 = 0.f, d1 = 0.f;
        #pragma unroll 8
        for (int k = 0; k < 32; k++) {
            float4 x = *reinterpret_cast<const float4*>(ra + 4 * k);
            float4 y = *reinterpret_cast<const float4*>(rb + 4 * k);
            d0 += x.x * y.x + x.y * y.y;
            d1 += x.z * y.z + x.w * y.w;
        }
        out[e] = d0 + d1;
    }
}

// ---------------------------------------------------------------------------
// Phase C: warp-local chunked tape scan.
// Block = (batch b, 128-channel group), 256 threads = 8 warps.
// Warp w owns local channels [16w, 16w+16); lane = (sq = lane>>3) slot quarter
// x (l8 = lane&7) channel pair. Thread tile: 32 slots x 2 channels = 32 ull.
// Per 8-step group (NO barriers):
//   phase1: partial u over own 32 slots; butterfly shfl over 4 sq -> all lanes
//   solve : 8x8 eager triangular with diag Gram, redundant across sq
//   phase3: tape += p (x) a from local a
// Barriers only around per-chunk staging (2 per chunk).
// ---------------------------------------------------------------------------
__global__ void __launch_bounds__(256, 2) scan_kernel(const float* __restrict__ vals)
{
    extern __shared__ __align__(16) float sm[];
    const int OF_SV = 8960;    // v: [64t][128c]
    const int OF_G  = 17152;   // diag gram: 512
    const int OF_W  = 17664;   // w gate: 64

    int tid  = threadIdx.x;
    int w    = tid >> 5;
    int lane = tid & 31;
    int l8   = lane & 7;
    int sq   = lane >> 3;
    int b    = blockIdx.x >> 3;
    int cg   = blockIdx.x & 7;
    int c0   = cg << 7;
    int c_lo = w * 16 + l8 * 2;          // local channel pair base
    uint32_t sb = smem_u32(sm);

    ull tp[16][2];
    #pragma unroll
    for (int m = 0; m < 16; m++) { tp[m][0] = 0ull; tp[m][1] = 0ull; }

    for (int q = 0; q < NQ_; q++) {
        int T0 = q * K_;
        __syncthreads();   // all warps done reading previous chunk's smem
        // ---- stage: sP tile is a straight linear copy (pre-swizzled) ----
        const float* gp = g_Pt + (size_t)(b * NQ_ + q) * (64 * 140);
        #pragma unroll
        for (int i = 0; i < 9; i++) {
            int idx = tid + 256 * i;
            if (idx < 2240) cpa16(sb + idx * 16, gp + idx * 4);
        }
        #pragma unroll
        for (int i = 0; i < 8; i++) {
            int idx = tid + 256 * i;
            int t = idx >> 5, seg = idx & 31;
            cpa16(sb + (OF_SV + t * 128 + seg * 4) * 4,
                  vals + ((size_t)(T0 + t) * B_ + b) * C_ + c0 + seg * 4);
        }
        if (tid < 128)
            cpa16(sb + (OF_G + tid * 4) * 4, g_Gd + (size_t)(b * NQ_ + q) * 512 + tid * 4);
        if (tid < 64)
            sm[OF_W + tid] = g_hd[(size_t)(T0 + tid) * B_ + b].w;
        cpa_wait();
        __syncthreads();

        for (int g = 0; g < 8; g++) {
            int t0 = g * 8;
            float u0[8], u1[8];

            // ---- phase1: partial u over own 32 slots ----
            #pragma unroll
            for (int tl = 0; tl < 8; tl++) {
                const ulonglong2* pr = reinterpret_cast<const ulonglong2*>(
                    sm + (t0 + tl) * 140 + sq * 36);
                ull x0 = 0ull, y0 = 0ull, x1 = 0ull, y1 = 0ull;
                #pragma unroll
                for (int k = 0; k < 8; k++) {
                    ulonglong2 p = pr[k];
                    x0 = fma2(p.x, tp[2 * k][0],     x0);
                    y0 = fma2(p.y, tp[2 * k + 1][0], y0);
                    x1 = fma2(p.x, tp[2 * k][1],     x1);
                    y1 = fma2(p.y, tp[2 * k + 1][1], y1);
                }
                float2 f0 = upk2(add2(x0, y0));
                float2 f1 = upk2(add2(x1, y1));
                u0[tl] = f0.x + f0.y;
                u1[tl] = f1.x + f1.y;
            }
            // ---- butterfly reduce over the 4 slot quarters (all lanes get sum)
            #pragma unroll
            for (int tl = 0; tl < 8; tl++) {
                u0[tl] += __shfl_xor_sync(0xffffffffu, u0[tl], 8);
                u1[tl] += __shfl_xor_sync(0xffffffffu, u1[tl], 8);
                u0[tl] += __shfl_xor_sync(0xffffffffu, u0[tl], 16);
                u1[tl] += __shfl_xor_sync(0xffffffffu, u1[tl], 16);
            }

            // ---- solve: eager 8x8 triangular (redundant across sq) ----
            float a0s[8], a1s[8];
            const float* Gg = sm + OF_G + g * 64;
            #pragma unroll
            for (int j = 0; j < 8; j++) {
                float uu0 = u0[j], uu1 = u1[j];
                #pragma unroll
                for (int jj = 0; jj < 8; jj++)
                    if (jj < j) {
                        float Gv = Gg[jj * 8 + j];
                        uu0 += a0s[jj] * Gv;
                        uu1 += a1s[jj] * Gv;
                    }
                float2 v2 = *reinterpret_cast<const float2*>(
                    sm + OF_SV + (t0 + j) * 128 + c_lo);
                float wg = sm[OF_W + t0 + j];
                a0s[j] = wg * (v2.x - uu0);
                a1s[j] = wg * (v2.y - uu1);
            }

            // ---- phase3: tape += p (x) a ----
            #pragma unroll
            for (int tl = 0; tl < 8; tl++) {
                const ulonglong2* pr = reinterpret_cast<const ulonglong2*>(
                    sm + (t0 + tl) * 140 + sq * 36);
                ull A0 = pk2(a0s[tl], a0s[tl]);
                ull A1 = pk2(a1s[tl], a1s[tl]);
                #pragma unroll
                for (int k = 0; k < 8; k++) {
                    ulonglong2 p = pr[k];
                    tp[2 * k][0]     = fma2(p.x, A0, tp[2 * k][0]);
                    tp[2 * k][1]     = fma2(p.x, A1, tp[2 * k][1]);
                    tp[2 * k + 1][0] = fma2(p.y, A0, tp[2 * k + 1][0]);
                    tp[2 * k + 1][1] = fma2(p.y, A1, tp[2 * k + 1][1]);
                }
            }
        }
    }

    // ---- write final tape ----
    #pragma unroll
    for (int m = 0; m < 16; m++) {
        float2 cv0 = upk2(tp[m][0]);     // slots (2m, 2m+1), channel c_lo
        float2 cv1 = upk2(tp[m][1]);     // slots (2m, 2m+1), channel c_lo+1
        int s0 = sq * 32 + 2 * m;
        float2* d0 = reinterpret_cast<float2*>(
            g_tape + ((size_t)s0 * B_ + b) * C_ + c0 + c_lo);
        float2* d1 = reinterpret_cast<float2*>(
            g_tape + ((size_t)(s0 + 1) * B_ + b) * C_ + c0 + c_lo);
        *d0 = make_float2(cv0.x, cv1.x);
        *d1 = make_float2(cv0.y, cv1.y);
    }
}

// ---------------------------------------------------------------------------
// Phase D: LayerNorm + out = h @ Wo^T + bo.
// ---------------------------------------------------------------------------
__global__ void __launch_bounds__(256) decode_kernel(
    const float* __restrict__ ln_g, const float* __restrict__ ln_b,
    const float* __restrict__ Wo,   const float* __restrict__ bo,
    float* __restrict__ out)
{
    __shared__ float sWo[V_ * C_];
    __shared__ float sred[2][8];
    __shared__ float sv2[8][V_];
    __shared__ float smv[2];

    int tid = threadIdx.x, lane = tid & 31, warp = tid >> 5;
    for (int i = tid; i < V_ * C_; i += 256) sWo[i] = Wo[i];
    float4 g4 = reinterpret_cast<const float4*>(ln_g)[tid];
    float4 e4 = reinterpret_cast<const float4*>(ln_b)[tid];
    __syncthreads();

    for (int j = 0; j < 16; j++) {
        int row = blockIdx.x * 16 + j;
        float4 x = reinterpret_cast<const float4*>(g_tape)[(size_t)row * (C_ / 4) + tid];
        float s = x.x + x.y + x.z + x.w;
        float qq = x.x*x.x + x.y*x.y + x.z*x.z + x.w*x.w;
        #pragma unroll
        for (int o = 16; o; o >>= 1) {
            s  += __shfl_xor_sync(0xffffffffu, s, o);
            qq += __shfl_xor_sync(0xffffffffu, qq, o);
        }
        if (lane == 0) { sred[0][warp] = s; sred[1][warp] = qq; }
        __syncthreads();
        if (tid == 0) {
            float ts = 0.f, tq = 0.f;
            #pragma unroll
            for (int k = 0; k < 8; k++) { ts += sred[0][k]; tq += sred[1][k]; }
            float mu = ts * (1.f / C_);
            smv[0] = mu;
            smv[1] = rsqrtf(tq * (1.f / C_) - mu * mu + LN_EPS_);
        }
        __syncthreads();
        float mu = smv[0], rstd = smv[1];
        float4 h;
        h.x = (x.x - mu) * rstd * g4.x + e4.x;
        h.y = (x.y - mu) * rstd * g4.y + e4.y;
        h.z = (x.z - mu) * rstd * g4.z + e4.z;
        h.w = (x.w - mu) * rstd * g4.w + e4.w;
        #pragma unroll
        for (int v = 0; v < V_; v++) {
            float4 wv = reinterpret_cast<const float4*>(sWo)[v * (C_ / 4) + tid];
            float pp = h.x*wv.x + h.y*wv.y + h.z*wv.z + h.w*wv.w;
            #pragma unroll
            for (int o = 16; o; o >>= 1) pp += __shfl_xor_sync(0xffffffffu, pp, o);
            if (lane == 0) sv2[warp][v] = pp;
        }
        __syncthreads();
        if (tid < V_) {
            float acc = bo[tid];
            #pragma unroll
            for (int k = 0; k < 8; k++) acc += sv2[k][tid];
            out[(size_t)row * V_ + tid] = acc;
        }
        __syncthreads();
    }
}

// ---------------------------------------------------------------------------
extern "C" void kernel_launch(void* const* d_in, const int* in_sizes, int n_in,
                              void* d_out, int out_size)
{
    const float* vals = (const float*)d_in[0];
    const float* Wd   = (const float*)d_in[1];
    const float* bd   = (const float*)d_in[2];
    const float* Wr   = (const float*)d_in[3];
    const float* br   = (const float*)d_in[4];
    const float* lng  = (const float*)d_in[5];
    const float* lnb  = (const float*)d_in[6];
    const float* Wo   = (const float*)d_in[7];
    const float* bo   = (const float*)d_in[8];
    float* out = (float*)d_out;

    const int SMEM_SCAN = (8960 + 8192 + 512 + 64) * 4;   // 70912 B
    cudaFuncSetAttribute(scan_kernel,
                         cudaFuncAttributeMaxDynamicSharedMemorySize, SMEM_SCAN);

    heads_kernel<<<(S_ * B_) / 8, 256>>>(vals, Wd, bd, Wr, br);
    pos_kernel<<<B_ / 8, 256>>>();
    gramd_kernel<<<B_ * NQ_, 256>>>();
    scan_kernel<<<B_ * (C_ / TS_), 256, SMEM_SCAN>>>(vals);
    decode_kernel<<<(TS_ * B_) / 16, 256>>>(lng, lnb, Wo, bo, out);
}

// round 8
// speedup vs baseline: 2.8148x; 2.8148x over previous
#include <cuda_runtime.h>
#include <cstdint>

#define S_  512
#define B_  64
#define C_  1024
#define V_  10
#define TS_ 128
#define K_  64            // chunk length
#define NQ_ (S_ / K_)     // 8 chunks
#define LN_EPS_ 1e-5f

typedef unsigned long long ull;

// Scratch (allocation-free rule: __device__ globals)
__device__ float  g_P[(size_t)S_ * B_ * TS_];    // pos [t][b][l] (16 MB)
__device__ float4 g_hd[(size_t)S_ * B_];         // (d0,d1,d2,w)
__device__ float  g_G4[(size_t)B_ * NQ_ * 256];  // 16 diag 4x4 Gram blocks per (b,q)
__device__ float  g_tape[(size_t)TS_ * B_ * C_]; // final tape [l][b][c] (32 MB)

// ---- packed fp32x2 helpers ----
__device__ __forceinline__ ull fma2(ull a, ull b, ull c) {
    ull d;
    asm("fma.rn.f32x2 %0, %1, %2, %3;" : "=l"(d) : "l"(a), "l"(b), "l"(c));
    return d;
}
__device__ __forceinline__ ull pk2(float lo, float hi) {
    ull r;
    asm("mov.b64 %0, {%1, %2};" : "=l"(r) : "f"(lo), "f"(hi));
    return r;
}
__device__ __forceinline__ float2 upk2(ull x) {
    float2 r;
    asm("mov.b64 {%0, %1}, %2;" : "=f"(r.x), "=f"(r.y) : "l"(x));
    return r;
}
__device__ __forceinline__ void cpa16(uint32_t s, const void* g) {
    asm volatile("cp.async.ca.shared.global [%0], [%1], 16;" :: "r"(s), "l"(g));
}
__device__ __forceinline__ void cpa_wait() {
    asm volatile("cp.async.commit_group;");
    asm volatile("cp.async.wait_group 0;" ::: "memory");
}
__device__ __forceinline__ uint32_t smem_u32(const void* p) {
    uint32_t a;
    asm("{ .reg .u64 t; cvta.to.shared.u64 t, %1; cvt.u32.u64 %0, t; }" : "=r"(a) : "l"(p));
    return a;
}

// ---------------------------------------------------------------------------
// Phase A: heads. dir = softmax(v@Wd^T+bd), w = sigmoid(v@Wr[1]+br[1]).
// ---------------------------------------------------------------------------
__global__ void __launch_bounds__(256) heads_kernel(
    const float* __restrict__ vals,
    const float* __restrict__ Wd, const float* __restrict__ bd,
    const float* __restrict__ Wr, const float* __restrict__ br)
{
    __shared__ float sW[4 * C_];
    int tid = threadIdx.x;
    for (int i = tid; i < 3 * C_; i += 256) sW[i] = Wd[i];
    for (int i = tid; i < C_;     i += 256) sW[3 * C_ + i] = Wr[C_ + i];
    __syncthreads();

    int wp = tid >> 5, lane = tid & 31;
    int row = blockIdx.x * 8 + wp;                 // row = t*B + b
    const float4* v4 = reinterpret_cast<const float4*>(vals + (size_t)row * C_);
    const float4* w4 = reinterpret_cast<const float4*>(sW);

    float a0 = 0.f, a1 = 0.f, a2 = 0.f, a3 = 0.f;
    for (int i = lane; i < C_ / 4; i += 32) {
        float4 v = v4[i];
        float4 w;
        w = w4[i];       a0 += v.x*w.x + v.y*w.y + v.z*w.z + v.w*w.w;
        w = w4[256 + i]; a1 += v.x*w.x + v.y*w.y + v.z*w.z + v.w*w.w;
        w = w4[512 + i]; a2 += v.x*w.x + v.y*w.y + v.z*w.z + v.w*w.w;
        w = w4[768 + i]; a3 += v.x*w.x + v.y*w.y + v.z*w.z + v.w*w.w;
    }
    #pragma unroll
    for (int o = 16; o; o >>= 1) {
        a0 += __shfl_xor_sync(0xffffffffu, a0, o);
        a1 += __shfl_xor_sync(0xffffffffu, a1, o);
        a2 += __shfl_xor_sync(0xffffffffu, a2, o);
        a3 += __shfl_xor_sync(0xffffffffu, a3, o);
    }
    if (lane == 0) {
        float z0 = a0 + bd[0], z1 = a1 + bd[1], z2 = a2 + bd[2];
        float m  = fmaxf(z0, fmaxf(z1, z2));
        float e0 = expf(z0 - m), e1 = expf(z1 - m), e2 = expf(z2 - m);
        float inv = 1.f / (e0 + e1 + e2);
        float wg  = 1.f / (1.f + expf(-(a3 + br[1])));
        g_hd[row] = make_float4(e0 * inv, e1 * inv, e2 * inv, wg);
    }
}

// ---------------------------------------------------------------------------
// Phase B: pos evolution. One warp per batch, 4 slots/lane, shuffle neighbors.
// ---------------------------------------------------------------------------
__global__ void __launch_bounds__(256) pos_kernel()
{
    int wp = threadIdx.x >> 5, lane = threadIdx.x & 31;
    int b = blockIdx.x * 8 + wp;
    float p0 = (lane == 0) ? 1.f : 0.f, p1 = 0.f, p2 = 0.f, p3 = 0.f;

    float4 D0 = g_hd[0 * B_ + b];
    float4 D1 = g_hd[1 * B_ + b];
    float4 D2 = g_hd[2 * B_ + b];
    float4 D3 = g_hd[3 * B_ + b];

    for (int t = 0; t < S_; t += 4) {
        #pragma unroll
        for (int k = 0; k < 4; k++) {
            int tt = t + k;
            float4* dst = reinterpret_cast<float4*>(g_P + ((size_t)tt * B_ + b) * TS_);
            dst[lane] = make_float4(p0, p1, p2, p3);
            float4 Dk = (k == 0) ? D0 : (k == 1) ? D1 : (k == 2) ? D2 : D3;
            float4 Dn = g_hd[(size_t)min(tt + 4, S_ - 1) * B_ + b];
            if (k == 0) D0 = Dn; else if (k == 1) D1 = Dn; else if (k == 2) D2 = Dn; else D3 = Dn;
            float d0 = Dk.x, d1 = Dk.y, d2 = Dk.z;
            float lw = __shfl_sync(0xffffffffu, p3, (lane + 31) & 31);
            float rw = __shfl_sync(0xffffffffu, p0, (lane + 1)  & 31);
            float n0 = p1 * d0 + p0 * d1 + lw * d2;
            float n1 = p2 * d0 + p1 * d1 + p0 * d2;
            float n2 = p3 * d0 + p2 * d1 + p1 * d2;
            float n3 = rw * d0 + p3 * d1 + p2 * d2;
            p0 = n0; p1 = n1; p2 = n2; p3 = n3;
        }
    }
}

// ---------------------------------------------------------------------------
// Phase B2: diag 4x4 Gram blocks: G4[(b,q)][g][jj][j] = p_{T0+4g+jj}.p_{T0+4g+j}
// ---------------------------------------------------------------------------
__global__ void __launch_bounds__(256) gram4_kernel()
{
    __shared__ float sPg[K_][132];
    int tid = threadIdx.x;
    const float* gp0 = g_P;
    int b = blockIdx.x >> 3, q = blockIdx.x & 7;
    int T0 = q * K_;

    for (int idx = tid; idx < K_ * TS_; idx += 256) {
        int t = idx >> 7, l = idx & 127;
        sPg[t][l] = gp0[((size_t)(T0 + t) * B_ + b) * TS_ + l];
    }
    __syncthreads();

    // one Gram entry per thread: e = g*16 + jj*4 + j
    int e = tid;
    int g = e >> 4, jj = (e >> 2) & 3, j = e & 3;
    const float* ra = sPg[g * 4 + jj];
    const float* rb = sPg[g * 4 + j];
    float d0 = 0.f, d1 = 0.f;
    #pragma unroll 8
    for (int k = 0; k < 32; k++) {
        float4 x = *reinterpret_cast<const float4*>(ra + 4 * k);
        float4 y = *reinterpret_cast<const float4*>(rb + 4 * k);
        d0 += x.x * y.x + x.y * y.y;
        d1 += x.z * y.z + x.w * y.w;
    }
    g_G4[(size_t)blockIdx.x * 256 + e] = d0 + d1;
}

// ---------------------------------------------------------------------------
// Phase C: warp-local chunked tape scan, group size 4.
// Block = (b, 128-channel group), 256 threads = 8 warps.
// Warp wp owns local channels [16wp, 16wp+16). lane = (sq = lane>>2) slot
// octant x (l4 = lane&3) channel quad. Tile: 16 slots x 4 ch = 32 ull.
// Per 4-step group (NO barriers): phase1 partial u over own 16 slots,
// 3-stage butterfly over 8 octants, redundant 4x4 eager solve, phase3.
// sP row layout: word(t,s) = t*160 + s + 4*(s>>4) (octant o at +20*o,
// conflict-free LDS.128 across octants).
// ---------------------------------------------------------------------------
__global__ void __launch_bounds__(256, 2) scan_kernel(const float* __restrict__ vals)
{
    extern __shared__ __align__(16) float sm[];
    const int OF_SV = 10240;   // v: [64t][128c]
    const int OF_G  = 18432;   // 256 gram floats
    const int OF_W  = 18688;   // 64 gate floats

    int tid  = threadIdx.x;
    int wp   = tid >> 5;
    int lane = tid & 31;
    int l4   = lane & 3;
    int sq   = lane >> 2;
    int b    = blockIdx.x >> 3;
    int cg   = blockIdx.x & 7;
    int c0   = cg << 7;
    int cl   = wp * 16 + l4 * 4;         // local channel quad base
    uint32_t sb = smem_u32(sm);
    const ull ZERO = 0ull;

    // tape tile: tp[sp][c] = slots (sq*16+2sp, +1), channel cl+c
    ull tp[8][4];
    #pragma unroll
    for (int sp = 0; sp < 8; sp++)
        #pragma unroll
        for (int c = 0; c < 4; c++) tp[sp][c] = 0ull;

    for (int q = 0; q < NQ_; q++) {
        int T0 = q * K_;
        __syncthreads();
        // ---- stage sP (padded), sv, G, w ----
        #pragma unroll
        for (int i = 0; i < 8; i++) {
            int idx = tid + 256 * i;               // 2048 16B segs
            int t = idx >> 5, seg = idx & 31;
            int dw = t * 160 + seg * 4 + 4 * (seg >> 2);
            cpa16(sb + dw * 4, g_P + ((size_t)(T0 + t) * B_ + b) * TS_ + seg * 4);
        }
        #pragma unroll
        for (int i = 0; i < 8; i++) {
            int idx = tid + 256 * i;
            int t = idx >> 5, seg = idx & 31;
            cpa16(sb + (OF_SV + t * 128 + seg * 4) * 4,
                  vals + ((size_t)(T0 + t) * B_ + b) * C_ + c0 + seg * 4);
        }
        if (tid < 64)
            cpa16(sb + (OF_G + tid * 4) * 4, g_G4 + (size_t)(b * NQ_ + q) * 256 + tid * 4);
        if (tid < 64)
            sm[OF_W + tid] = g_hd[(size_t)(T0 + tid) * B_ + b].w;
        cpa_wait();
        __syncthreads();

        for (int grp = 0; grp < 16; grp++) {
            int t0 = grp * 4;
            float u[4][4];     // [j][c]

            // ---- phase1: partial u over own 16 slots ----
            #pragma unroll
            for (int j = 0; j < 4; j++) {
                const ulonglong2* pr = reinterpret_cast<const ulonglong2*>(
                    sm + (t0 + j) * 160 + sq * 20);
                ulonglong2 q0 = pr[0], q1 = pr[1], q2 = pr[2], q3 = pr[3];
                #pragma unroll
                for (int c = 0; c < 4; c++) {
                    ull e = fma2(q0.x, tp[0][c], ZERO);
                    ull o = fma2(q0.y, tp[1][c], ZERO);
                    e = fma2(q1.x, tp[2][c], e);
                    o = fma2(q1.y, tp[3][c], o);
                    e = fma2(q2.x, tp[4][c], e);
                    o = fma2(q2.y, tp[5][c], o);
                    e = fma2(q3.x, tp[6][c], e);
                    o = fma2(q3.y, tp[7][c], o);
                    float2 fe = upk2(e), fo = upk2(o);
                    u[j][c] = (fe.x + fe.y) + (fo.x + fo.y);
                }
            }
            // ---- butterfly over 8 octants (lane bits 2,3,4) ----
            #pragma unroll
            for (int j = 0; j < 4; j++)
                #pragma unroll
                for (int c = 0; c < 4; c++) {
                    float uu = u[j][c];
                    uu += __shfl_xor_sync(0xffffffffu, uu, 4);
                    uu += __shfl_xor_sync(0xffffffffu, uu, 8);
                    uu += __shfl_xor_sync(0xffffffffu, uu, 16);
                    u[j][c] = uu;
                }

            // ---- solve: eager 4x4 triangular, redundant across octants ----
            float a[4][4];     // [j][c]
            const float* Gg = sm + OF_G + grp * 16;
            #pragma unroll
            for (int j = 0; j < 4; j++) {
                float4 vv = *reinterpret_cast<const float4*>(
                    sm + OF_SV + (t0 + j) * 128 + cl);
                float wg = sm[OF_W + t0 + j];
                float uu0 = u[j][0], uu1 = u[j][1], uu2 = u[j][2], uu3 = u[j][3];
                #pragma unroll
                for (int jj = 0; jj < 4; jj++)
                    if (jj < j) {
                        float Gv = Gg[jj * 4 + j];
                        uu0 += a[jj][0] * Gv;
                        uu1 += a[jj][1] * Gv;
                        uu2 += a[jj][2] * Gv;
                        uu3 += a[jj][3] * Gv;
                    }
                a[j][0] = wg * (vv.x - uu0);
                a[j][1] = wg * (vv.y - uu1);
                a[j][2] = wg * (vv.z - uu2);
                a[j][3] = wg * (vv.w - uu3);
            }

            // ---- phase3: tape += p (x) a ----
            #pragma unroll
            for (int j = 0; j < 4; j++) {
                const ulonglong2* pr = reinterpret_cast<const ulonglong2*>(
                    sm + (t0 + j) * 160 + sq * 20);
                ulonglong2 q0 = pr[0], q1 = pr[1], q2 = pr[2], q3 = pr[3];
                #pragma unroll
                for (int c = 0; c < 4; c++) {
                    ull A = pk2(a[j][c], a[j][c]);
                    tp[0][c] = fma2(q0.x, A, tp[0][c]);
                    tp[1][c] = fma2(q0.y, A, tp[1][c]);
                    tp[2][c] = fma2(q1.x, A, tp[2][c]);
                    tp[3][c] = fma2(q1.y, A, tp[3][c]);
                    tp[4][c] = fma2(q2.x, A, tp[4][c]);
                    tp[5][c] = fma2(q2.y, A, tp[5][c]);
                    tp[6][c] = fma2(q3.x, A, tp[6][c]);
                    tp[7][c] = fma2(q3.y, A, tp[7][c]);
                }
            }
        }
    }

    // ---- write final tape ----
    #pragma unroll
    for (int sp = 0; sp < 8; sp++) {
        float2 r0 = upk2(tp[sp][0]), r1 = upk2(tp[sp][1]);
        float2 r2 = upk2(tp[sp][2]), r3 = upk2(tp[sp][3]);
        int s0 = sq * 16 + 2 * sp;
        float4* d0 = reinterpret_cast<float4*>(
            g_tape + ((size_t)s0 * B_ + b) * C_ + c0 + cl);
        float4* d1 = reinterpret_cast<float4*>(
            g_tape + ((size_t)(s0 + 1) * B_ + b) * C_ + c0 + cl);
        *d0 = make_float4(r0.x, r1.x, r2.x, r3.x);
        *d1 = make_float4(r0.y, r1.y, r2.y, r3.y);
    }
}

// ---------------------------------------------------------------------------
// Phase D: LayerNorm + out = h @ Wo^T + bo.  Warp-per-row, no block barriers
// after the Wo stage. grid = TS*B/8.
// ---------------------------------------------------------------------------
__global__ void __launch_bounds__(256) decode_kernel(
    const float* __restrict__ ln_g, const float* __restrict__ ln_b,
    const float* __restrict__ Wo,   const float* __restrict__ bo,
    float* __restrict__ out)
{
    __shared__ float sWo[V_ * C_];   // 40 KB
    int tid = threadIdx.x, lane = tid & 31, wp = tid >> 5;
    for (int i = tid; i < V_ * C_; i += 256) sWo[i] = Wo[i];
    __syncthreads();

    int row = blockIdx.x * 8 + wp;      // row = l*B + b
    const float4* src = reinterpret_cast<const float4*>(g_tape + (size_t)row * C_);
    float4 x[8];
    #pragma unroll
    for (int k = 0; k < 8; k++) x[k] = src[lane + 32 * k];

    float s = 0.f, qq = 0.f;
    #pragma unroll
    for (int k = 0; k < 8; k++) {
        s  += (x[k].x + x[k].y) + (x[k].z + x[k].w);
        qq += (x[k].x*x[k].x + x[k].y*x[k].y) + (x[k].z*x[k].z + x[k].w*x[k].w);
    }
    #pragma unroll
    for (int o = 16; o; o >>= 1) {
        s  += __shfl_xor_sync(0xffffffffu, s, o);
        qq += __shfl_xor_sync(0xffffffffu, qq, o);
    }
    float mu = s * (1.f / C_);
    float rstd = rsqrtf(qq * (1.f / C_) - mu * mu + LN_EPS_);

    const float4* g4 = reinterpret_cast<const float4*>(ln_g);
    const float4* e4 = reinterpret_cast<const float4*>(ln_b);
    #pragma unroll
    for (int k = 0; k < 8; k++) {
        float4 gg = g4[lane + 32 * k];
        float4 ee = e4[lane + 32 * k];
        x[k].x = (x[k].x - mu) * rstd * gg.x + ee.x;
        x[k].y = (x[k].y - mu) * rstd * gg.y + ee.y;
        x[k].z = (x[k].z - mu) * rstd * gg.z + ee.z;
        x[k].w = (x[k].w - mu) * rstd * gg.w + ee.w;
    }

    #pragma unroll
    for (int v = 0; v < V_; v++) {
        const float4* wv = reinterpret_cast<const float4*>(sWo + v * C_);
        float pp = 0.f;
        #pragma unroll
        for (int k = 0; k < 8; k++) {
            float4 w = wv[lane + 32 * k];
            pp += (x[k].x*w.x + x[k].y*w.y) + (x[k].z*w.z + x[k].w*w.w);
        }
        #pragma unroll
        for (int o = 16; o; o >>= 1) pp += __shfl_xor_sync(0xffffffffu, pp, o);
        if (lane == 0) out[(size_t)row * V_ + v] = pp + bo[v];
    }
}

// ---------------------------------------------------------------------------
extern "C" void kernel_launch(void* const* d_in, const int* in_sizes, int n_in,
                              void* d_out, int out_size)
{
    const float* vals = (const float*)d_in[0];
    const float* Wd   = (const float*)d_in[1];
    const float* bd   = (const float*)d_in[2];
    const float* Wr   = (const float*)d_in[3];
    const float* br   = (const float*)d_in[4];
    const float* lng  = (const float*)d_in[5];
    const float* lnb  = (const float*)d_in[6];
    const float* Wo   = (const float*)d_in[7];
    const float* bo   = (const float*)d_in[8];
    float* out = (float*)d_out;

    const int SMEM_SCAN = (10240 + 8192 + 256 + 64) * 4;   // 75008 B
    cudaFuncSetAttribute(scan_kernel,
                         cudaFuncAttributeMaxDynamicSharedMemorySize, SMEM_SCAN);

    heads_kernel<<<(S_ * B_) / 8, 256>>>(vals, Wd, bd, Wr, br);
    pos_kernel<<<B_ / 8, 256>>>();
    gram4_kernel<<<B_ * NQ_, 256>>>();
    scan_kernel<<<B_ * (C_ / TS_), 256, SMEM_SCAN>>>(vals);
    decode_kernel<<<(TS_ * B_) / 8, 256>>>(lng, lnb, Wo, bo, out);
}